// round 7
// baseline (speedup 1.0000x reference)
#include <cuda_runtime.h>

// FixedRadiusNearNeighbors: B=8, N=16384, S=2048, radius 0.1, K=64.
// First 64 ascending indices with sqrdist <= 0.01f, padded with first hit,
// written as float32. Distance arithmetic is FROZEN (passed R6):
//   cc  = ((cx*cx + cy*cy) + cz*cz)            f32 RN mul/add
//   dot = fma(pz,cz, fma(py,cy, fma(px,cx,0))) ascending-k FMA chain
//   pp  = ((px*px + py*py) + pz*pz)            f32 RN mul/add
//   d   = (cc - 2*dot) + pp ; hit = !(d > 0.01f)
//
// R7 change: 2 queries per warp -> each LDS.128 feeds 2 distance tests,
// halving smem traffic per test (L1 was 75% = bottleneck).

#define BATCH  8
#define NPTS   16384
#define NQ     2048
#define NNB    64
#define TILE   2048      // 2048 * 16B = 32 KB smem
#define WPB    8         // warps per block
#define QPW    2         // queries per warp
#define QPB    (WPB * QPW)   // 16 queries per block
#define R2     0.01f

__global__ __launch_bounds__(256)
void frnn_kernel(const float* __restrict__ pos,
                 const int*   __restrict__ cent,
                 float*       __restrict__ out)
{
    __shared__ float4 sp4[TILE];         // {x, y, z, pp}
    __shared__ int done_count;

    const int lane = threadIdx.x & 31;
    const int warp = threadIdx.x >> 5;
    const int q0   = blockIdx.x * QPB + warp * QPW;   // first query of this warp
    const int b    = q0 >> 11;                         // q0 / NQ (QPB divides NQ)
    const float* posb = pos + (size_t)b * NPTS * 3;

    // Two centers per warp.
    const int c0 = cent[q0];
    const int c1 = cent[q0 + 1];
    const float c0x = posb[c0 * 3 + 0], c0y = posb[c0 * 3 + 1], c0z = posb[c0 * 3 + 2];
    const float c1x = posb[c1 * 3 + 0], c1y = posb[c1 * 3 + 1], c1z = posb[c1 * 3 + 2];
    const float cc0 = __fadd_rn(__fadd_rn(__fmul_rn(c0x, c0x), __fmul_rn(c0y, c0y)),
                                __fmul_rn(c0z, c0z));
    const float cc1 = __fadd_rn(__fadd_rn(__fmul_rn(c1x, c1x), __fmul_rn(c1y, c1y)),
                                __fmul_rn(c1z, c1z));

    float* orow0 = out + (size_t)q0 * NNB;
    float* orow1 = orow0 + NNB;

    if (threadIdx.x == 0) done_count = 0;

    int   cnt0 = 0,    cnt1 = 0;
    float first0 = 0.f, first1 = 0.f;
    bool  done0 = false, done1 = false;

    for (int base = 0; base < NPTS; base += TILE) {
        __syncthreads();                 // orders done_count + tile reuse
        if (done_count == QPB) break;

        // Cooperative tile load; precompute pp with reference rounding.
        const float* src = posb + (size_t)base * 3;
        #pragma unroll 2
        for (int i = threadIdx.x; i < TILE; i += 256) {
            float px = src[i * 3 + 0];
            float py = src[i * 3 + 1];
            float pz = src[i * 3 + 2];
            float pp = __fadd_rn(__fadd_rn(__fmul_rn(px, px), __fmul_rn(py, py)),
                                 __fmul_rn(pz, pz));
            sp4[i] = make_float4(px, py, pz, pp);
        }
        __syncthreads();

        if (!(done0 && done1)) {
            #pragma unroll 4
            for (int i = lane; i < TILE; i += 32) {
                float4 p = sp4[i];       // one LDS.128 feeds both queries

                if (!done0) {            // warp-uniform branch
                    float dot = __fmaf_rn(p.x, c0x, 0.0f);
                    dot = __fmaf_rn(p.y, c0y, dot);
                    dot = __fmaf_rn(p.z, c0z, dot);
                    float d = __fadd_rn(__fsub_rn(cc0, __fmul_rn(2.0f, dot)), p.w);
                    bool hit = !(d > R2);
                    unsigned mask = __ballot_sync(0xffffffffu, hit);
                    if (mask) {
                        if (cnt0 == 0) {
                            int fi = __shfl_sync(0xffffffffu, base + i, __ffs(mask) - 1);
                            first0 = (float)fi;
                        }
                        if (hit) {
                            int slot = cnt0 + __popc(mask & ((1u << lane) - 1u));
                            if (slot < NNB) orow0[slot] = (float)(base + i);
                        }
                        cnt0 += __popc(mask);
                        if (cnt0 >= NNB) {
                            done0 = true;
                            if (lane == 0) atomicAdd(&done_count, 1);
                        }
                    }
                }

                if (!done1) {            // warp-uniform branch
                    float dot = __fmaf_rn(p.x, c1x, 0.0f);
                    dot = __fmaf_rn(p.y, c1y, dot);
                    dot = __fmaf_rn(p.z, c1z, dot);
                    float d = __fadd_rn(__fsub_rn(cc1, __fmul_rn(2.0f, dot)), p.w);
                    bool hit = !(d > R2);
                    unsigned mask = __ballot_sync(0xffffffffu, hit);
                    if (mask) {
                        if (cnt1 == 0) {
                            int fi = __shfl_sync(0xffffffffu, base + i, __ffs(mask) - 1);
                            first1 = (float)fi;
                        }
                        if (hit) {
                            int slot = cnt1 + __popc(mask & ((1u << lane) - 1u));
                            if (slot < NNB) orow1[slot] = (float)(base + i);
                        }
                        cnt1 += __popc(mask);
                        if (cnt1 >= NNB) {
                            done1 = true;
                            if (lane == 0) atomicAdd(&done_count, 1);
                        }
                    }
                }

                if (done0 && done1) break;
            }
        }
    }

    // Pad tails with first hit (group_first semantics).
    if (cnt0 > NNB) cnt0 = NNB;
    if (cnt1 > NNB) cnt1 = NNB;
    for (int s = cnt0 + lane; s < NNB; s += 32) orow0[s] = first0;
    for (int s = cnt1 + lane; s < NNB; s += 32) orow1[s] = first1;
}

extern "C" void kernel_launch(void* const* d_in, const int* in_sizes, int n_in,
                              void* d_out, int out_size)
{
    const float* pos;
    const int*   cent;
    if (in_sizes[0] > in_sizes[1]) {
        pos  = (const float*)d_in[0];
        cent = (const int*)  d_in[1];
    } else {
        pos  = (const float*)d_in[1];
        cent = (const int*)  d_in[0];
    }
    float* out = (float*)d_out;                  // (8,2048,64) as float32

    dim3 grid(BATCH * NQ / QPB);                 // 1024 blocks
    dim3 block(256);
    frnn_kernel<<<grid, block>>>(pos, cent, out);
}

// round 8
// speedup vs baseline: 1.4149x; 1.4149x over previous
#include <cuda_runtime.h>
#include <cstdint>

// FixedRadiusNearNeighbors: B=8, N=16384, S=2048, radius 0.1, K=64.
// First 64 ascending indices with sqrdist <= 0.01f, padded with first hit,
// written as float32. Distance arithmetic FROZEN (bit-identical to R6 pass):
//   cc  = ((cx*cx + cy*cy) + cz*cz)            f32 RN mul/add
//   dot = fma(pz,cz, fma(py,cy, fma(px,cx,0))) ascending-k FMA chain
//   d   = fma(dot, -2, cc) + pp     [== (cc - 2*dot) + pp : 2*dot is exact]
//   pp  = ((px*px + py*py) + pz*pz)            f32 RN mul/add
//   hit = !(d > 0.01f)
//
// R8: packed f32x2 math (FFMA2), 2 points/lane (i, i+32), 2 queries/warp.

#define BATCH  8
#define NPTS   16384
#define NQ     2048
#define NNB    64
#define TILE   2048              // points per smem tile
#define NPAIR  (TILE / 2)        // 1024 pairs
#define WPB    8
#define QPW    2
#define QPB    (WPB * QPW)       // 16 queries per block
#define R2     0.01f

__device__ __forceinline__ uint64_t pk2(float a, float b) {
    return (uint64_t)__float_as_uint(a) | ((uint64_t)__float_as_uint(b) << 32);
}
__device__ __forceinline__ uint64_t fma2(uint64_t a, uint64_t b, uint64_t c) {
    uint64_t d;
    asm("fma.rn.f32x2 %0, %1, %2, %3;" : "=l"(d) : "l"(a), "l"(b), "l"(c));
    return d;
}
__device__ __forceinline__ uint64_t add2(uint64_t a, uint64_t b) {
    uint64_t d;
    asm("add.rn.f32x2 %0, %1, %2;" : "=l"(d) : "l"(a), "l"(b));
    return d;
}
__device__ __forceinline__ void lds128(uint64_t& a, uint64_t& b, const float4* p) {
    uint32_t sa = (uint32_t)__cvta_generic_to_shared(p);
    asm volatile("ld.shared.v2.b64 {%0, %1}, [%2];" : "=l"(a), "=l"(b) : "r"(sa));
}

__global__ __launch_bounds__(256)
void frnn_kernel(const float* __restrict__ pos,
                 const int*   __restrict__ cent,
                 float*       __restrict__ out)
{
    __shared__ float4 arrA[NPAIR];   // {x0, x1, y0, y1} for pair (i, i+32)
    __shared__ float4 arrB[NPAIR];   // {z0, z1, pp0, pp1}
    __shared__ int done_count;

    const int lane = threadIdx.x & 31;
    const int warp = threadIdx.x >> 5;
    const int q0   = blockIdx.x * QPB + warp * QPW;
    const int b    = q0 >> 11;                      // q0 / NQ
    const float* posb = pos + (size_t)b * NPTS * 3;

    // Centers (packed duplicated for f32x2 lanes).
    const int ci0 = cent[q0], ci1 = cent[q0 + 1];
    const float a0x = posb[ci0*3+0], a0y = posb[ci0*3+1], a0z = posb[ci0*3+2];
    const float a1x = posb[ci1*3+0], a1y = posb[ci1*3+1], a1z = posb[ci1*3+2];
    const float cc0 = __fadd_rn(__fadd_rn(__fmul_rn(a0x,a0x), __fmul_rn(a0y,a0y)),
                                __fmul_rn(a0z,a0z));
    const float cc1 = __fadd_rn(__fadd_rn(__fmul_rn(a1x,a1x), __fmul_rn(a1y,a1y)),
                                __fmul_rn(a1z,a1z));
    const uint64_t c0x2 = pk2(a0x,a0x), c0y2 = pk2(a0y,a0y), c0z2 = pk2(a0z,a0z);
    const uint64_t c1x2 = pk2(a1x,a1x), c1y2 = pk2(a1y,a1y), c1z2 = pk2(a1z,a1z);
    const uint64_t cc02 = pk2(cc0,cc0), cc12 = pk2(cc1,cc1);
    const uint64_t neg2 = pk2(-2.0f,-2.0f);
    const uint64_t zer2 = 0ull;

    float* orow0 = out + (size_t)q0 * NNB;
    float* orow1 = orow0 + NNB;

    if (threadIdx.x == 0) done_count = 0;

    int   cnt0 = 0,     cnt1 = 0;
    float first0 = 0.f, first1 = 0.f;
    bool  done0 = false, done1 = false;

    for (int base = 0; base < NPTS; base += TILE) {
        __syncthreads();
        if (done_count == QPB) break;

        // Tile load: pair (p0, p0+32); pp precomputed with frozen rounding.
        const float* src = posb + (size_t)base * 3;
        #pragma unroll
        for (int s = threadIdx.x; s < NPAIR; s += 256) {
            int j = s >> 5, l = s & 31;
            int p0 = (j << 6) + l;                 // tile-local index
            const float* g0 = src + p0 * 3;
            const float* g1 = g0 + 96;             // +32 points
            float x0 = g0[0], y0 = g0[1], z0 = g0[2];
            float x1 = g1[0], y1 = g1[1], z1 = g1[2];
            float pp0 = __fadd_rn(__fadd_rn(__fmul_rn(x0,x0), __fmul_rn(y0,y0)),
                                  __fmul_rn(z0,z0));
            float pp1 = __fadd_rn(__fadd_rn(__fmul_rn(x1,x1), __fmul_rn(y1,y1)),
                                  __fmul_rn(z1,z1));
            arrA[s] = make_float4(x0, x1, y0, y1);
            arrB[s] = make_float4(z0, z1, pp0, pp1);
        }
        __syncthreads();

        if (done0 && done1) continue;   // keep loading tiles for other warps

        #pragma unroll 2
        for (int it = 0; it < TILE / 64; ++it) {
            const int s  = (it << 5) + lane;
            const int i0 = base + (it << 6) + lane;   // group A index
            uint64_t x2, y2, z2, pp2;
            lds128(x2, y2, arrA + s);
            lds128(z2, pp2, arrB + s);

            if (!done0) {                 // warp-uniform
                uint64_t t = fma2(x2, c0x2, zer2);
                t = fma2(y2, c0y2, t);
                t = fma2(z2, c0z2, t);
                t = fma2(t, neg2, cc02);              // cc - 2*dot (exact equiv)
                uint64_t d2 = add2(t, pp2);
                float dl = __uint_as_float((uint32_t)d2);
                float dh = __uint_as_float((uint32_t)(d2 >> 32));
                unsigned mA = __ballot_sync(0xffffffffu, !(dl > R2));
                unsigned mB = __ballot_sync(0xffffffffu, !(dh > R2));
                if (mA | mB) {
                    unsigned below = (1u << lane) - 1u;
                    if (cnt0 == 0) {
                        int fi = mA ? __shfl_sync(0xffffffffu, i0, __ffs(mA)-1)
                                    : __shfl_sync(0xffffffffu, i0+32, __ffs(mB)-1);
                        first0 = (float)fi;
                    }
                    if (mA & (1u << lane)) {
                        int slot = cnt0 + __popc(mA & below);
                        if (slot < NNB) orow0[slot] = (float)i0;
                    }
                    int na = __popc(mA);
                    if (mB & (1u << lane)) {
                        int slot = cnt0 + na + __popc(mB & below);
                        if (slot < NNB) orow0[slot] = (float)(i0 + 32);
                    }
                    cnt0 += na + __popc(mB);
                    if (cnt0 >= NNB) {
                        done0 = true;
                        if (lane == 0) atomicAdd(&done_count, 1);
                    }
                }
            }

            if (!done1) {                 // warp-uniform
                uint64_t t = fma2(x2, c1x2, zer2);
                t = fma2(y2, c1y2, t);
                t = fma2(z2, c1z2, t);
                t = fma2(t, neg2, cc12);
                uint64_t d2 = add2(t, pp2);
                float dl = __uint_as_float((uint32_t)d2);
                float dh = __uint_as_float((uint32_t)(d2 >> 32));
                unsigned mA = __ballot_sync(0xffffffffu, !(dl > R2));
                unsigned mB = __ballot_sync(0xffffffffu, !(dh > R2));
                if (mA | mB) {
                    unsigned below = (1u << lane) - 1u;
                    if (cnt1 == 0) {
                        int fi = mA ? __shfl_sync(0xffffffffu, i0, __ffs(mA)-1)
                                    : __shfl_sync(0xffffffffu, i0+32, __ffs(mB)-1);
                        first1 = (float)fi;
                    }
                    if (mA & (1u << lane)) {
                        int slot = cnt1 + __popc(mA & below);
                        if (slot < NNB) orow1[slot] = (float)i0;
                    }
                    int na = __popc(mA);
                    if (mB & (1u << lane)) {
                        int slot = cnt1 + na + __popc(mB & below);
                        if (slot < NNB) orow1[slot] = (float)(i0 + 32);
                    }
                    cnt1 += na + __popc(mB);
                    if (cnt1 >= NNB) {
                        done1 = true;
                        if (lane == 0) atomicAdd(&done_count, 1);
                    }
                }
            }

            if (done0 && done1) break;
        }
    }

    // Pad tails with first hit (group_first semantics).
    if (cnt0 > NNB) cnt0 = NNB;
    if (cnt1 > NNB) cnt1 = NNB;
    for (int s = cnt0 + lane; s < NNB; s += 32) orow0[s] = first0;
    for (int s = cnt1 + lane; s < NNB; s += 32) orow1[s] = first1;
}

extern "C" void kernel_launch(void* const* d_in, const int* in_sizes, int n_in,
                              void* d_out, int out_size)
{
    const float* pos;
    const int*   cent;
    if (in_sizes[0] > in_sizes[1]) {
        pos  = (const float*)d_in[0];
        cent = (const int*)  d_in[1];
    } else {
        pos  = (const float*)d_in[1];
        cent = (const int*)  d_in[0];
    }
    float* out = (float*)d_out;                  // (8,2048,64) as float32

    dim3 grid(BATCH * NQ / QPB);                 // 1024 blocks
    dim3 block(256);
    frnn_kernel<<<grid, block>>>(pos, cent, out);
}

// round 9
// speedup vs baseline: 1.7034x; 1.2039x over previous
#include <cuda_runtime.h>
#include <cstdint>

// FixedRadiusNearNeighbors: B=8, N=16384, S=2048, radius 0.1, K=64.
// First 64 ascending indices with sqrdist <= 0.01f, padded with first hit,
// float32 output. Distance arithmetic FROZEN (bit-identical to R6 pass):
//   cc  = ((cx*cx + cy*cy) + cz*cz)            f32 RN mul/add
//   dot = fma(pz,cz, fma(py,cy, fma(px,cx,0))) ascending-k FMA chain
//   d   = fma(dot,-2,cc) + pp   [== (cc-2*dot)+pp, 2*dot exact]
//   pp  = ((px*px + py*py) + pz*pz)            f32 RN mul/add
//   hit = d <= 0.01f   (== !(d>R2) for finite d)
//
// R9: branch-free hot path — finished queries get cc=1e30 (no more hits),
// single __any_sync gate over 4 packed predicates, ballots only on hit,
// unroll 4 for immediate-offset LDS.

#define BATCH  8
#define NPTS   16384
#define NQ     2048
#define NNB    64
#define TILE   2048
#define NPAIR  (TILE / 2)
#define WPB    8
#define QPW    2
#define QPB    (WPB * QPW)       // 16
#define R2     0.01f

__device__ __forceinline__ uint64_t pk2(float a, float b) {
    return (uint64_t)__float_as_uint(a) | ((uint64_t)__float_as_uint(b) << 32);
}
__device__ __forceinline__ float lo2(uint64_t v) { return __uint_as_float((uint32_t)v); }
__device__ __forceinline__ float hi2(uint64_t v) { return __uint_as_float((uint32_t)(v >> 32)); }
__device__ __forceinline__ uint64_t fma2(uint64_t a, uint64_t b, uint64_t c) {
    uint64_t d;
    asm("fma.rn.f32x2 %0, %1, %2, %3;" : "=l"(d) : "l"(a), "l"(b), "l"(c));
    return d;
}
__device__ __forceinline__ uint64_t add2(uint64_t a, uint64_t b) {
    uint64_t d;
    asm("add.rn.f32x2 %0, %1, %2;" : "=l"(d) : "l"(a), "l"(b));
    return d;
}
__device__ __forceinline__ void lds128(uint64_t& a, uint64_t& b, const float4* p) {
    uint32_t sa = (uint32_t)__cvta_generic_to_shared(p);
    asm volatile("ld.shared.v2.b64 {%0, %1}, [%2];" : "=l"(a), "=l"(b) : "r"(sa));
}

__global__ __launch_bounds__(256)
void frnn_kernel(const float* __restrict__ pos,
                 const int*   __restrict__ cent,
                 float*       __restrict__ out)
{
    __shared__ float4 arrA[NPAIR];   // {x0, x1, y0, y1} for pair (i, i+32)
    __shared__ float4 arrB[NPAIR];   // {z0, z1, pp0, pp1}
    __shared__ int done_count;

    const int lane = threadIdx.x & 31;
    const int warp = threadIdx.x >> 5;
    const int q0   = blockIdx.x * QPB + warp * QPW;
    const int b    = q0 >> 11;
    const float* posb = pos + (size_t)b * NPTS * 3;

    const int ci0 = cent[q0], ci1 = cent[q0 + 1];
    const float a0x = posb[ci0*3+0], a0y = posb[ci0*3+1], a0z = posb[ci0*3+2];
    const float a1x = posb[ci1*3+0], a1y = posb[ci1*3+1], a1z = posb[ci1*3+2];
    const float cc0 = __fadd_rn(__fadd_rn(__fmul_rn(a0x,a0x), __fmul_rn(a0y,a0y)),
                                __fmul_rn(a0z,a0z));
    const float cc1 = __fadd_rn(__fadd_rn(__fmul_rn(a1x,a1x), __fmul_rn(a1y,a1y)),
                                __fmul_rn(a1z,a1z));
    const uint64_t c0x2 = pk2(a0x,a0x), c0y2 = pk2(a0y,a0y), c0z2 = pk2(a0z,a0z);
    const uint64_t c1x2 = pk2(a1x,a1x), c1y2 = pk2(a1y,a1y), c1z2 = pk2(a1z,a1z);
    const uint64_t neg2 = pk2(-2.0f,-2.0f);
    const uint64_t KILL = pk2(1e30f, 1e30f);

    uint64_t cc02 = pk2(cc0,cc0), cc12 = pk2(cc1,cc1);   // set to KILL when done

    float* orow0 = out + (size_t)q0 * NNB;
    float* orow1 = orow0 + NNB;

    if (threadIdx.x == 0) done_count = 0;

    int   cnt0 = 0,     cnt1 = 0;
    float first0 = 0.f, first1 = 0.f;

    for (int base = 0; base < NPTS; base += TILE) {
        __syncthreads();
        if (done_count == QPB) break;

        // Tile load: pair (p, p+32); pp with frozen rounding.
        const float* src = posb + (size_t)base * 3;
        #pragma unroll
        for (int s = threadIdx.x; s < NPAIR; s += 256) {
            int j = s >> 5, l = s & 31;
            int p0 = (j << 6) + l;
            const float* g0 = src + p0 * 3;
            const float* g1 = g0 + 96;
            float x0 = g0[0], y0 = g0[1], z0 = g0[2];
            float x1 = g1[0], y1 = g1[1], z1 = g1[2];
            float pp0 = __fadd_rn(__fadd_rn(__fmul_rn(x0,x0), __fmul_rn(y0,y0)),
                                  __fmul_rn(z0,z0));
            float pp1 = __fadd_rn(__fadd_rn(__fmul_rn(x1,x1), __fmul_rn(y1,y1)),
                                  __fmul_rn(z1,z1));
            arrA[s] = make_float4(x0, x1, y0, y1);
            arrB[s] = make_float4(z0, z1, pp0, pp1);
        }
        __syncthreads();

        if (cnt0 >= NNB && cnt1 >= NNB) continue;   // warp idle; still loads tiles

        #pragma unroll 4
        for (int it = 0; it < TILE / 64; ++it) {
            const int s = (it << 5) + lane;
            uint64_t x2, y2, z2, pp2;
            lds128(x2, y2, arrA + s);
            lds128(z2, pp2, arrB + s);

            // Query 0 packed distance
            uint64_t t0 = fma2(x2, c0x2, 0ull);
            t0 = fma2(y2, c0y2, t0);
            t0 = fma2(z2, c0z2, t0);
            t0 = fma2(t0, neg2, cc02);
            uint64_t d0 = add2(t0, pp2);
            // Query 1 packed distance
            uint64_t t1 = fma2(x2, c1x2, 0ull);
            t1 = fma2(y2, c1y2, t1);
            t1 = fma2(z2, c1z2, t1);
            t1 = fma2(t1, neg2, cc12);
            uint64_t d1 = add2(t1, pp2);

            float d0l = lo2(d0), d0h = hi2(d0);
            float d1l = lo2(d1), d1h = hi2(d1);
            bool anyhit = (d0l <= R2) | (d0h <= R2) | (d1l <= R2) | (d1h <= R2);

            if (__any_sync(0xffffffffu, anyhit)) {   // warp-uniform, rare (~47%)
                const int i0 = base + (it << 6) + lane;
                const unsigned below = (1u << lane) - 1u;

                unsigned mA = __ballot_sync(0xffffffffu, d0l <= R2);
                unsigned mB = __ballot_sync(0xffffffffu, d0h <= R2);
                if (mA | mB) {
                    if (cnt0 == 0) {
                        int fi = mA ? __shfl_sync(0xffffffffu, i0, __ffs(mA)-1)
                                    : __shfl_sync(0xffffffffu, i0+32, __ffs(mB)-1);
                        first0 = (float)fi;
                    }
                    if (mA & (1u << lane)) {
                        int slot = cnt0 + __popc(mA & below);
                        if (slot < NNB) orow0[slot] = (float)i0;
                    }
                    int na = __popc(mA);
                    if (mB & (1u << lane)) {
                        int slot = cnt0 + na + __popc(mB & below);
                        if (slot < NNB) orow0[slot] = (float)(i0 + 32);
                    }
                    cnt0 += na + __popc(mB);
                    if (cnt0 >= NNB) {
                        cc02 = KILL;               // query 0 stops hitting
                        if (lane == 0) atomicAdd(&done_count, 1);
                    }
                }

                mA = __ballot_sync(0xffffffffu, d1l <= R2);
                mB = __ballot_sync(0xffffffffu, d1h <= R2);
                if (mA | mB) {
                    if (cnt1 == 0) {
                        int fi = mA ? __shfl_sync(0xffffffffu, i0, __ffs(mA)-1)
                                    : __shfl_sync(0xffffffffu, i0+32, __ffs(mB)-1);
                        first1 = (float)fi;
                    }
                    if (mA & (1u << lane)) {
                        int slot = cnt1 + __popc(mA & below);
                        if (slot < NNB) orow1[slot] = (float)i0;
                    }
                    int na = __popc(mA);
                    if (mB & (1u << lane)) {
                        int slot = cnt1 + na + __popc(mB & below);
                        if (slot < NNB) orow1[slot] = (float)(i0 + 32);
                    }
                    cnt1 += na + __popc(mB);
                    if (cnt1 >= NNB) {
                        cc12 = KILL;               // query 1 stops hitting
                        if (lane == 0) atomicAdd(&done_count, 1);
                    }
                }

                if (cnt0 >= NNB && cnt1 >= NNB) break;
            }
        }
    }

    // Pad tails with first hit (group_first semantics).
    if (cnt0 > NNB) cnt0 = NNB;
    if (cnt1 > NNB) cnt1 = NNB;
    for (int s = cnt0 + lane; s < NNB; s += 32) orow0[s] = first0;
    for (int s = cnt1 + lane; s < NNB; s += 32) orow1[s] = first1;
}

extern "C" void kernel_launch(void* const* d_in, const int* in_sizes, int n_in,
                              void* d_out, int out_size)
{
    const float* pos;
    const int*   cent;
    if (in_sizes[0] > in_sizes[1]) {
        pos  = (const float*)d_in[0];
        cent = (const int*)  d_in[1];
    } else {
        pos  = (const float*)d_in[1];
        cent = (const int*)  d_in[0];
    }
    float* out = (float*)d_out;                  // (8,2048,64) as float32

    dim3 grid(BATCH * NQ / QPB);                 // 1024 blocks
    dim3 block(256);
    frnn_kernel<<<grid, block>>>(pos, cent, out);
}